// round 15
// baseline (speedup 1.0000x reference)
#include <cuda_runtime.h>
#include <math.h>
#include <stdint.h>

#define TT 2048
#define BB 64
#define KIN 256
#define HH 256

typedef unsigned long long ull;

// ---------------------------------------------------------------------------
// f32x2 helpers (Blackwell packed fp32 pipe)
// ---------------------------------------------------------------------------
__device__ __forceinline__ ull ffma2(ull a, ull b, ull c) {
    ull d;
    asm("fma.rn.f32x2 %0, %1, %2, %3;" : "=l"(d) : "l"(a), "l"(b), "l"(c));
    return d;
}
__device__ __forceinline__ ull fadd2(ull a, ull b) {
    ull d;
    asm("add.rn.f32x2 %0, %1, %2;" : "=l"(d) : "l"(a), "l"(b));
    return d;
}
__device__ __forceinline__ ull fdup2(float a) {
    ull d; unsigned u = __float_as_uint(a);
    asm("mov.b64 %0, {%1, %2};" : "=l"(d) : "r"(u), "r"(u));
    return d;
}
__device__ __forceinline__ ull fpack2(float a, float b) {
    ull d;
    asm("mov.b64 %0, {%1, %2};" : "=l"(d)
        : "r"(__float_as_uint(a)), "r"(__float_as_uint(b)));
    return d;
}
__device__ __forceinline__ float2 funpack2(ull a) {
    unsigned lo, hi;
    asm("mov.b64 {%0, %1}, %2;" : "=r"(lo), "=r"(hi) : "l"(a));
    return make_float2(__uint_as_float(lo), __uint_as_float(hi));
}
__device__ __forceinline__ uint32_t smem_u32(const void* p) {
    uint32_t a;
    asm("{ .reg .u64 t; cvta.to.shared.u64 t, %1; cvt.u32.u64 %0, t; }"
        : "=r"(a) : "l"(p));
    return a;
}
__device__ __forceinline__ uint32_t mapa_peer(uint32_t local, uint32_t peer) {
    uint32_t r;
    asm("mapa.shared::cluster.u32 %0, %1, %2;" : "=r"(r) : "r"(local), "r"(peer));
    return r;
}
__device__ __forceinline__ void st_async_b64(uint32_t raddr, ull v, uint32_t rbar) {
    asm volatile(
        "st.async.shared::cluster.mbarrier::complete_tx::bytes.b64 [%0], %1, [%2];"
        :: "r"(raddr), "l"(v), "r"(rbar) : "memory");
}
__device__ __forceinline__ void mbar_init(uint32_t addr, uint32_t cnt) {
    asm volatile("mbarrier.init.shared.b64 [%0], %1;" :: "r"(addr), "r"(cnt) : "memory");
}
__device__ __forceinline__ void mbar_expect_tx(uint32_t addr, uint32_t bytes) {
    asm volatile("mbarrier.arrive.expect_tx.shared.b64 _, [%0], %1;"
                 :: "r"(addr), "r"(bytes) : "memory");
}
__device__ __forceinline__ void mbar_wait_parity(uint32_t addr, uint32_t parity) {
    asm volatile(
        "{\n\t"
        ".reg .pred P;\n\t"
        "WL_%=:\n\t"
        "mbarrier.try_wait.parity.acquire.cluster.shared::cta.b64 P, [%0], %1, 0x989680;\n\t"
        "@!P bra WL_%=;\n\t"
        "}" :: "r"(addr), "r"(parity) : "memory");
}
__device__ __forceinline__ void cp_async16(uint32_t saddr, const void* gptr) {
    asm volatile("cp.async.cg.shared.global [%0], [%1], 16;"
                 :: "r"(saddr), "l"(gptr) : "memory");
}
__device__ __forceinline__ void cp_commit() {
    asm volatile("cp.async.commit_group;" ::: "memory");
}
__device__ __forceinline__ void cp_wait0() {
    asm volatile("cp.async.wait_group 0;" ::: "memory");
}
#define CLUSTER_SYNC_() do { \
    asm volatile("barrier.cluster.arrive.aligned;" ::: "memory"); \
    asm volatile("barrier.cluster.wait.aligned;" ::: "memory"); \
} while (0)

// ---------------------------------------------------------------------------
// Fused kernel: serial recurrence (round-12 proven cluster protocol) with the
// xp input-projection GEMM FOLDED INTO the scan's idle latency slots.
//
// xp computed in 8-step windows (m=8 W_ih reuse): per step each thread does
// 8 k-iters: acc[p] += dup2(W_ih[row][k]) * pack(x[t2p][k], x[t2p+1][k]).
// x staged 2 windows ahead via cp.async (no stall) + transpose; xp results
// stored to a double-buffered ring one window before use; bias folded in.
//
// Shared memory map (floats, dynamic):
//   W_s  [64 kk][4 c][136]   own-half W_ih, bank-tuned (row+8c -> 1-wf LDS.32)
//   xs   [2][4 c][64 kk][12] transposed x windows (8c banks -> 1-wf LDS.128)
//   xraw [8][256]            cp.async landing pad (same-thread transpose)
//   ring [2][128 row][8 t']  xp results (+bias)
//   bias_s[128], hsm[2][144], rsm[2][128]
// ---------------------------------------------------------------------------
#define HP   36
#define HBUF (4 * HP)                 // 144
#define W_S_OFF   0                   // 64*544 = 34816 floats
#define XS_OFF    34816               // 2*3104 = 6208
#define XRAW_OFF  41024               // 2048
#define RING_OFF  43072               // 2048
#define BIAS_OFF  45120               // 128
#define HSM_OFF   45248               // 2*144 = 288
#define RSM_OFF   45536               // 2*128 = 256
#define SMEM_FLOATS 45792
#define SMEM_BYTES  (SMEM_FLOATS * 4) // 183168

__global__ __launch_bounds__(512, 1) __cluster_dims__(2, 1, 1)
void rnn_scan_kernel(const float* __restrict__ x,
                     const float* __restrict__ Wih,
                     const float* __restrict__ b_ih,
                     const float* __restrict__ b_hh,
                     const float* __restrict__ Whh,
                     float* __restrict__ out)
{
    extern __shared__ __align__(16) float sm[];
    float* W_s    = sm + W_S_OFF;
    float* xs     = sm + XS_OFF;
    float* xraw   = sm + XRAW_OFF;
    float* ring   = sm + RING_OFF;
    float* bias_s = sm + BIAS_OFF;
    float* hsm    = sm + HSM_OFF;     // [2][HBUF]
    float* rsm    = sm + RSM_OFF;     // [2][128]
    __shared__ __align__(8) ull mbars[2];

    const int tid = threadIdx.x;
    const unsigned rank = blockIdx.x & 1u;
    const int batch = blockIdx.x >> 1;
    const int c  = tid & 3;                     // K sub-chunk / role lane
    const int gg = (tid >> 2) & 63;             // row-pair index within half
    const int xrow = tid >> 2;                  // xp row (local own-half, 0..127)
    const bool sender = (tid >= 256);           // warps 8-15: compute peer rows
    const int half_base = sender ? (int)((rank ^ 1u) * 128) : (int)(rank * 128);
    const int r0 = half_base + 2 * gg;          // W_hh target rows r0, r0+1
    const int k0 = (int)rank * 128 + 32 * c;    // own-K chunk

    const uint32_t mb0 = smem_u32(&mbars[0]);
    const uint32_t mb1 = smem_u32(&mbars[1]);
    const uint32_t rsm_addr = smem_u32(rsm);
    const uint32_t peer = rank ^ 1u;
    const uint32_t peer_mb0 = mapa_peer(mb0, peer);
    const uint32_t peer_mb1 = mapa_peer(mb1, peer);
    const uint32_t peer_rsm = mapa_peer(rsm_addr, peer);

    // Register-resident W_hh: rows r0, r0+1 x K-chunk [k0, k0+32).
    ull w0[16], w1[16];
    {
        const ull* p0 = (const ull*)(Whh + (size_t)r0 * HH + k0);
        const ull* p1 = (const ull*)(Whh + (size_t)(r0 + 1) * HH + k0);
#pragma unroll
        for (int i = 0; i < 16; i++) { w0[i] = p0[i]; w1[i] = p1[i]; }
    }

    // ---- Prologue: W_ih own half -> W_s (bank-tuned layout) ----
    for (int i4 = tid; i4 < 8192; i4 += 512) {
        int row = i4 >> 6;                       // 0..127
        int k4  = (i4 & 63) * 4;
        float4 wv = *(const float4*)(Wih + (size_t)((int)rank * 128 + row) * KIN + k4);
        int cc = k4 >> 6, kk = k4 & 63;
        float* b = W_s + cc * 136 + row;
        b[(kk + 0) * 544] = wv.x; b[(kk + 1) * 544] = wv.y;
        b[(kk + 2) * 544] = wv.z; b[(kk + 3) * 544] = wv.w;
    }
    if (tid < 128) bias_s[tid] = b_ih[rank * 128u + tid] + b_hh[rank * 128u + tid];
    if (tid < HBUF) hsm[tid] = 0.0f;             // h_{-1} = 0 (buffer 0)
    if (tid == 0) { mbar_init(mb0, 1); mbar_init(mb1, 1); }

    // ---- Prologue: stage + transpose x windows 0, 1 ----
    const int tpr = tid >> 6;                    // t' 0..7
    const int k4s = (tid & 63) * 4;
    const int ccs = k4s >> 6, kks = k4s & 63;
    const uint32_t xraw_addr = smem_u32(xraw) + (unsigned)tid * 16u;
    for (int wp = 0; wp < 2; wp++) {
        const float* gsrc = x + ((size_t)(wp * 8 + tpr) * BB + batch) * HH + k4s;
        cp_async16(xraw_addr, gsrc);
        cp_commit();
        cp_wait0();
        float4 xv4 = *(const float4*)(xraw + tid * 4);
        float* dst = xs + wp * 3104 + ccs * 776 + tpr;
        dst[(kks + 0) * 12] = xv4.x; dst[(kks + 1) * 12] = xv4.y;
        dst[(kks + 2) * 12] = xv4.z; dst[(kks + 3) * 12] = xv4.w;
    }
    __syncthreads();                              // W_s, bias, xs[0], xs[1] ready

    // ---- Prologue: burst-compute xp window 0 into ring[0] ----
    ull acc0 = 0ull, acc1 = 0ull, acc2 = 0ull, acc3 = 0ull;
    for (int ss = 0; ss < 8; ss++) {
        const float* Wp = W_s + (8 * ss) * 544 + c * 136 + xrow;
        const float* Xp = xs + c * 776 + (8 * ss) * 12;   // slot 0
#pragma unroll
        for (int it = 0; it < 8; it++) {
            ull wd = fdup2(Wp[it * 544]);
            ulonglong2 xq0 = *(const ulonglong2*)(Xp + it * 12);
            ulonglong2 xq1 = *(const ulonglong2*)(Xp + it * 12 + 4);
            acc0 = ffma2(wd, xq0.x, acc0); acc1 = ffma2(wd, xq0.y, acc1);
            acc2 = ffma2(wd, xq1.x, acc2); acc3 = ffma2(wd, xq1.y, acc3);
        }
    }
#pragma unroll
    for (int m = 1; m < 4; m <<= 1) {
        acc0 = fadd2(acc0, __shfl_xor_sync(0xffffffffu, acc0, m));
        acc1 = fadd2(acc1, __shfl_xor_sync(0xffffffffu, acc1, m));
        acc2 = fadd2(acc2, __shfl_xor_sync(0xffffffffu, acc2, m));
        acc3 = fadd2(acc3, __shfl_xor_sync(0xffffffffu, acc3, m));
    }
    if (c == 0) {
        ull bd = fdup2(bias_s[xrow]);
        ull* rdst = (ull*)&ring[(size_t)xrow * 8];
        rdst[0] = fadd2(acc0, bd); rdst[1] = fadd2(acc1, bd);
        rdst[2] = fadd2(acc2, bd); rdst[3] = fadd2(acc3, bd);
    }
    acc0 = acc1 = acc2 = acc3 = 0ull;
    __syncthreads();
    CLUSTER_SYNC_();                              // peer mbars visible

    const size_t tstride = (size_t)BB * HH;
    float* outp = out + (size_t)batch * HH + r0 + c;   // receivers c<2: row r0+c

    for (int t = 0; t < TT; t++) {
        const unsigned par = (unsigned)t & 1u;
        const int s = t & 7;
        const int w = t >> 3;
        const uint32_t mbar      = par ? mb1 : mb0;
        const uint32_t peer_mbar = par ? peer_mb1 : peer_mb0;
        const unsigned phase     = ((unsigned)t >> 1) & 1u;

        if (tid == 0) mbar_expect_tx(mbar, 512);  // 64 x 8 B from peer, step t

        // Early, off-critical-path: receivers fetch this step's xp from ring.
        float xpv = 0.0f;
        if (!sender && c < 2) xpv = ring[(size_t)(w & 1) * 1024 + (2 * gg + c) * 8 + s];

        // ---- W_hh partial dot over own-K chunk [32c, 32c+32): rows r0, r0+1 ----
        const ulonglong2* hp = (const ulonglong2*)(hsm + par * HBUF + HP * c);
        ull a0A = 0ull, a1A = 0ull, a0B = 0ull, a1B = 0ull;
#pragma unroll
        for (int i = 0; i < 4; i++) {
            ulonglong2 hq = hp[i];
            a0A = ffma2(w0[2 * i],     hq.x, a0A);
            a1A = ffma2(w1[2 * i],     hq.x, a1A);
            a0A = ffma2(w0[2 * i + 1], hq.y, a0A);
            a1A = ffma2(w1[2 * i + 1], hq.y, a1A);
        }
#pragma unroll
        for (int i = 4; i < 8; i++) {
            ulonglong2 hq = hp[i];
            a0B = ffma2(w0[2 * i],     hq.x, a0B);
            a1B = ffma2(w1[2 * i],     hq.x, a1B);
            a0B = ffma2(w0[2 * i + 1], hq.y, a0B);
            a1B = ffma2(w1[2 * i + 1], hq.y, a1B);
        }
        float2 u0 = funpack2(fadd2(a0A, a0B));
        float2 u1 = funpack2(fadd2(a1A, a1B));
        float s0 = u0.x + u0.y;
        float s1 = u1.x + u1.y;
#pragma unroll
        for (int m = 1; m < 4; m <<= 1) {
            s0 += __shfl_xor_sync(0xffffffffu, s0, m);
            s1 += __shfl_xor_sync(0xffffffffu, s1, m);
        }

        // Senders fire partials for peer's rows ASAP.
        if (sender && c == 0) {
            uint32_t raddr = peer_rsm + (par * 128u + 2u * (unsigned)gg) * 4u;
            st_async_b64(raddr, fpack2(s0, s1), peer_mbar);
        }

        // ---- xp pipeline (fills sender slack / hides receiver flight) ----
        if (s == 0 && w + 2 < 256) {              // stage x[window w+2] (no stall)
            const float* gsrc = x + ((size_t)((w + 2) * 8 + tpr) * BB + batch) * HH + k4s;
            cp_async16(xraw_addr, gsrc);
            cp_commit();
        }
        if (s == 1 && w + 2 < 256) {              // transpose into xs[w&1]
            cp_wait0();
            float4 xv4 = *(const float4*)(xraw + tid * 4);
            float* dst = xs + (w & 1) * 3104 + ccs * 776 + tpr;
            dst[(kks + 0) * 12] = xv4.x; dst[(kks + 1) * 12] = xv4.y;
            dst[(kks + 2) * 12] = xv4.z; dst[(kks + 3) * 12] = xv4.w;
        }
        if (w + 1 < 256) {                        // 8 k-iters of window w+1
            const float* Wp = W_s + (8 * s) * 544 + c * 136 + xrow;
            const float* Xp = xs + ((w + 1) & 1) * 3104 + c * 776 + (8 * s) * 12;
#pragma unroll
            for (int it = 0; it < 8; it++) {
                ull wd = fdup2(Wp[it * 544]);
                ulonglong2 xq0 = *(const ulonglong2*)(Xp + it * 12);
                ulonglong2 xq1 = *(const ulonglong2*)(Xp + it * 12 + 4);
                acc0 = ffma2(wd, xq0.x, acc0); acc1 = ffma2(wd, xq0.y, acc1);
                acc2 = ffma2(wd, xq1.x, acc2); acc3 = ffma2(wd, xq1.y, acc3);
            }
            if (s == 7) {                         // window done: reduce + store
#pragma unroll
                for (int m = 1; m < 4; m <<= 1) {
                    acc0 = fadd2(acc0, __shfl_xor_sync(0xffffffffu, acc0, m));
                    acc1 = fadd2(acc1, __shfl_xor_sync(0xffffffffu, acc1, m));
                    acc2 = fadd2(acc2, __shfl_xor_sync(0xffffffffu, acc2, m));
                    acc3 = fadd2(acc3, __shfl_xor_sync(0xffffffffu, acc3, m));
                }
                if (c == 0) {
                    ull bd = fdup2(bias_s[xrow]);
                    ull* rdst = (ull*)&ring[(size_t)((w + 1) & 1) * 1024 + xrow * 8];
                    rdst[0] = fadd2(acc0, bd); rdst[1] = fadd2(acc1, bd);
                    rdst[2] = fadd2(acc2, bd); rdst[3] = fadd2(acc3, bd);
                }
                acc0 = acc1 = acc2 = acc3 = 0ull;
            }
        }

        // ---- Receivers: wait for peer partials, combine, tanh, publish ----
        if (!sender && c < 2) {
            mbar_wait_parity(mbar, phase);
            const int li = 2 * gg + c;
            float pr = rsm[par * 128 + li];
            float hn = tanhf((c ? s1 : s0) + pr + xpv);
            hsm[(par ^ 1u) * HBUF + HP * (li >> 5) + (li & 31)] = hn;
            outp[(size_t)t * tstride] = hn;
        }

        __syncthreads();   // h half + ring/xs writes visible; rsm[par] retired
    }
    CLUSTER_SYNC_();
}

// ---------------------------------------------------------------------------
// Launch — single fused kernel, no scratch, no separate GEMM.
// ---------------------------------------------------------------------------
extern "C" void kernel_launch(void* const* d_in, const int* in_sizes, int n_in,
                              void* d_out, int out_size)
{
    const float* x    = (const float*)d_in[0];
    const float* Wih  = (const float*)d_in[1];
    const float* Whh  = (const float*)d_in[2];
    const float* b_ih = (const float*)d_in[3];
    const float* b_hh = (const float*)d_in[4];
    float* out = (float*)d_out;

    cudaFuncSetAttribute(rnn_scan_kernel,
                         cudaFuncAttributeMaxDynamicSharedMemorySize, SMEM_BYTES);
    rnn_scan_kernel<<<2 * BB, 512, SMEM_BYTES>>>(x, Wih, b_ih, b_hh, Whh, out);
}

// round 16
// speedup vs baseline: 1.3746x; 1.3746x over previous
#include <cuda_runtime.h>
#include <math.h>
#include <stdint.h>

#define TT 2048
#define BB 64
#define KIN 256
#define HH 256

typedef unsigned long long ull;

// Scratch for precomputed input projection xp[t][b][h] (134 MB device global).
__device__ float g_xp[(size_t)TT * BB * HH];

// ---------------------------------------------------------------------------
// f32x2 helpers (Blackwell packed fp32 pipe)
// ---------------------------------------------------------------------------
__device__ __forceinline__ ull ffma2(ull a, ull b, ull c) {
    ull d;
    asm("fma.rn.f32x2 %0, %1, %2, %3;" : "=l"(d) : "l"(a), "l"(b), "l"(c));
    return d;
}
__device__ __forceinline__ ull fadd2(ull a, ull b) {
    ull d;
    asm("add.rn.f32x2 %0, %1, %2;" : "=l"(d) : "l"(a), "l"(b));
    return d;
}
__device__ __forceinline__ ull fdup2(float a) {
    ull d; unsigned u = __float_as_uint(a);
    asm("mov.b64 %0, {%1, %2};" : "=l"(d) : "r"(u), "r"(u));
    return d;
}
__device__ __forceinline__ ull fpack2(float a, float b) {
    ull d;
    asm("mov.b64 %0, {%1, %2};" : "=l"(d)
        : "r"(__float_as_uint(a)), "r"(__float_as_uint(b)));
    return d;
}
__device__ __forceinline__ float2 funpack2(ull a) {
    unsigned lo, hi;
    asm("mov.b64 {%0, %1}, %2;" : "=r"(lo), "=r"(hi) : "l"(a));
    return make_float2(__uint_as_float(lo), __uint_as_float(hi));
}
// Branch-free fast tanh: tanh(x) = 1 - 2/(1 + e^{2x}), e^{2x} via ex2.approx.
// Saturation-safe: x->+inf => e=inf => rcp=0 => 1;  x->-inf => e=0 => -1.
// Error ~1e-6 per evaluation (2-ulp ex2 + 1-ulp rcp), vs 1e-3 rel_err budget.
__device__ __forceinline__ float fast_tanhf(float x) {
    float u = x * 2.8853900817779268f;     // 2*log2(e)
    float e, r;
    asm("ex2.approx.f32 %0, %1;" : "=f"(e) : "f"(u));
    float d = e + 1.0f;
    asm("rcp.approx.f32 %0, %1;" : "=f"(r) : "f"(d));
    return fmaf(-2.0f, r, 1.0f);
}
__device__ __forceinline__ uint32_t smem_u32(const void* p) {
    uint32_t a;
    asm("{ .reg .u64 t; cvta.to.shared.u64 t, %1; cvt.u32.u64 %0, t; }"
        : "=r"(a) : "l"(p));
    return a;
}
__device__ __forceinline__ uint32_t mapa_peer(uint32_t local, uint32_t peer) {
    uint32_t r;
    asm("mapa.shared::cluster.u32 %0, %1, %2;" : "=r"(r) : "r"(local), "r"(peer));
    return r;
}
__device__ __forceinline__ void st_async_b64(uint32_t raddr, ull v, uint32_t rbar) {
    asm volatile(
        "st.async.shared::cluster.mbarrier::complete_tx::bytes.b64 [%0], %1, [%2];"
        :: "r"(raddr), "l"(v), "r"(rbar) : "memory");
}
__device__ __forceinline__ void mbar_init(uint32_t addr, uint32_t cnt) {
    asm volatile("mbarrier.init.shared.b64 [%0], %1;" :: "r"(addr), "r"(cnt) : "memory");
}
__device__ __forceinline__ void mbar_expect_tx(uint32_t addr, uint32_t bytes) {
    asm volatile("mbarrier.arrive.expect_tx.shared.b64 _, [%0], %1;"
                 :: "r"(addr), "r"(bytes) : "memory");
}
__device__ __forceinline__ void mbar_wait_parity(uint32_t addr, uint32_t parity) {
    asm volatile(
        "{\n\t"
        ".reg .pred P;\n\t"
        "WL_%=:\n\t"
        "mbarrier.try_wait.parity.acquire.cluster.shared::cta.b64 P, [%0], %1, 0x989680;\n\t"
        "@!P bra WL_%=;\n\t"
        "}" :: "r"(addr), "r"(parity) : "memory");
}
#define CLUSTER_SYNC_() do { \
    asm volatile("barrier.cluster.arrive.aligned;" ::: "memory"); \
    asm volatile("barrier.cluster.wait.aligned;" ::: "memory"); \
} while (0)

// ---------------------------------------------------------------------------
// Kernel 1: xp[m][n] = x[m][:] . W_ih[n][:] + b_ih[n] + b_hh[n]
// f32x2 GEMM, 128x128 tile, BK=16, 256 threads, per-thread 8x8.
// A stored PRE-DUPLICATED in smem, double-buffered, register-prefetched LDG.
// (round-14 version, unchanged)
// ---------------------------------------------------------------------------
#define AS_STR 264
#define BS_STR 132
#define AS_BUF (16 * AS_STR)
#define BS_BUF (16 * BS_STR)
#define GEMM_SMEM ((2 * AS_BUF + 2 * BS_BUF) * 4)   // 50688 bytes

__global__ __launch_bounds__(256, 2) void xp_gemm_kernel(
    const float* __restrict__ x,
    const float* __restrict__ Wih,
    const float* __restrict__ b_ih,
    const float* __restrict__ b_hh)
{
    extern __shared__ float sm[];
    float* Asb = sm;
    float* Bsb = sm + 2 * AS_BUF;

    const int tid = threadIdx.x;
    const int m0 = blockIdx.x * 128;
    const int n0 = blockIdx.y * 128;
    const int ty = tid >> 4;
    const int tx = tid & 15;

    const int row0 = tid >> 2;
    const int row1 = (tid + 256) >> 2;
    const int c4   = (tid & 3) * 4;

    ull acc[8][4];
#pragma unroll
    for (int i = 0; i < 8; i++)
#pragma unroll
        for (int p = 0; p < 4; p++) acc[i][p] = 0ull;

    float4 avr[2], bvr[2];

    avr[0] = *(const float4*)(x   + (size_t)(m0 + row0) * KIN + c4);
    avr[1] = *(const float4*)(x   + (size_t)(m0 + row1) * KIN + c4);
    bvr[0] = *(const float4*)(Wih + (size_t)(n0 + row0) * KIN + c4);
    bvr[1] = *(const float4*)(Wih + (size_t)(n0 + row1) * KIN + c4);
    {
        float* As = Asb;
        float* Bs = Bsb;
        const int rows[2] = { row0, row1 };
#pragma unroll
        for (int l = 0; l < 2; l++) {
            float av[4] = { avr[l].x, avr[l].y, avr[l].z, avr[l].w };
            float bv[4] = { bvr[l].x, bvr[l].y, bvr[l].z, bvr[l].w };
#pragma unroll
            for (int j = 0; j < 4; j++) {
                *(ull*)&As[(c4 + j) * AS_STR + 2 * rows[l]] = fdup2(av[j]);
                Bs[(c4 + j) * BS_STR + rows[l]] = bv[j];
            }
        }
    }
    __syncthreads();

    for (int kt = 0; kt < 16; kt++) {
        const int buf = kt & 1;
        if (kt < 15) {
            const int ko = (kt + 1) * 16;
            avr[0] = *(const float4*)(x   + (size_t)(m0 + row0) * KIN + ko + c4);
            avr[1] = *(const float4*)(x   + (size_t)(m0 + row1) * KIN + ko + c4);
            bvr[0] = *(const float4*)(Wih + (size_t)(n0 + row0) * KIN + ko + c4);
            bvr[1] = *(const float4*)(Wih + (size_t)(n0 + row1) * KIN + ko + c4);
        }

        const float* As = Asb + buf * AS_BUF;
        const float* Bs = Bsb + buf * BS_BUF;
#pragma unroll
        for (int k = 0; k < 16; k++) {
            const ulonglong2* ap = (const ulonglong2*)&As[k * AS_STR + 16 * ty];
            ulonglong2 aq0 = ap[0];
            ulonglong2 aq1 = ap[1];
            ulonglong2 aq2 = ap[2];
            ulonglong2 aq3 = ap[3];
            ulonglong2 bq0 = *(const ulonglong2*)&Bs[k * BS_STR + 8 * tx];
            ulonglong2 bq1 = *(const ulonglong2*)&Bs[k * BS_STR + 8 * tx + 4];
            ull ad[8] = { aq0.x, aq0.y, aq1.x, aq1.y, aq2.x, aq2.y, aq3.x, aq3.y };
            ull bp[4] = { bq0.x, bq0.y, bq1.x, bq1.y };
#pragma unroll
            for (int i = 0; i < 8; i++)
#pragma unroll
                for (int p = 0; p < 4; p++)
                    acc[i][p] = ffma2(ad[i], bp[p], acc[i][p]);
        }

        if (kt < 15) {
            float* Asn = Asb + (buf ^ 1) * AS_BUF;
            float* Bsn = Bsb + (buf ^ 1) * BS_BUF;
            const int rows[2] = { row0, row1 };
#pragma unroll
            for (int l = 0; l < 2; l++) {
                float av[4] = { avr[l].x, avr[l].y, avr[l].z, avr[l].w };
                float bv[4] = { bvr[l].x, bvr[l].y, bvr[l].z, bvr[l].w };
#pragma unroll
                for (int j = 0; j < 4; j++) {
                    *(ull*)&Asn[(c4 + j) * AS_STR + 2 * rows[l]] = fdup2(av[j]);
                    Bsn[(c4 + j) * BS_STR + rows[l]] = bv[j];
                }
            }
            __syncthreads();
        }
    }

    float bb[8];
#pragma unroll
    for (int j = 0; j < 8; j++) {
        int n = n0 + tx * 8 + j;
        bb[j] = b_ih[n] + b_hh[n];
    }
#pragma unroll
    for (int i = 0; i < 8; i++) {
        float* dst = g_xp + (size_t)(m0 + ty * 8 + i) * HH + n0 + tx * 8;
        float2 c0 = funpack2(acc[i][0]);
        float2 c1 = funpack2(acc[i][1]);
        float2 c2 = funpack2(acc[i][2]);
        float2 c3 = funpack2(acc[i][3]);
        float4 v0 = make_float4(c0.x + bb[0], c0.y + bb[1], c1.x + bb[2], c1.y + bb[3]);
        float4 v1 = make_float4(c2.x + bb[4], c2.y + bb[5], c3.x + bb[6], c3.y + bb[7]);
        *(float4*)dst       = v0;
        *(float4*)(dst + 4) = v1;
    }
}

// ---------------------------------------------------------------------------
// Kernel 2: serial recurrence — round-12/14 proven cluster protocol, with:
//   NEW (a): fast_tanhf (ex2.approx + rcp.approx, branch-free) replacing the
//            slow non-fast-math libdevice tanhf on the critical receiver tail
//   NEW (b): receivers form (s + xv) BEFORE the mbar wait; post-wake work is
//            one FADD + fast tanh + stores
// Everything else identical: senders = warps 8-15, 64 x 8 B st.async/step,
// two mbarriers by t&1, phase (t>>1)&1, HP-padded conflict-free h.
// ---------------------------------------------------------------------------
#define HP   36
#define HBUF (4 * HP)                 // 144
#define RBUF 128

__global__ __launch_bounds__(512, 1) __cluster_dims__(2, 1, 1)
void rnn_scan_kernel(const float* __restrict__ Whh, float* __restrict__ out)
{
    __shared__ __align__(16) float hsm[2][HBUF];
    __shared__ __align__(16) float rsm[2][RBUF];
    __shared__ __align__(8)  ull   mbars[2];

    const int tid = threadIdx.x;
    const unsigned rank = blockIdx.x & 1u;
    const int batch = blockIdx.x >> 1;
    const int c  = tid & 3;
    const int gg = (tid >> 2) & 63;
    const bool sender = (tid >= 256);
    const int half_base = sender ? (int)((rank ^ 1u) * 128) : (int)(rank * 128);
    const int r0 = half_base + 2 * gg;
    const int k0 = (int)rank * 128 + 32 * c;

    const uint32_t mb0 = smem_u32(&mbars[0]);
    const uint32_t mb1 = smem_u32(&mbars[1]);
    const uint32_t rsm_addr = smem_u32(&rsm[0][0]);
    const uint32_t peer = rank ^ 1u;
    const uint32_t peer_mb0 = mapa_peer(mb0, peer);
    const uint32_t peer_mb1 = mapa_peer(mb1, peer);
    const uint32_t peer_rsm = mapa_peer(rsm_addr, peer);

    ull w0[16], w1[16];
    {
        const ull* p0 = (const ull*)(Whh + (size_t)r0 * HH + k0);
        const ull* p1 = (const ull*)(Whh + (size_t)(r0 + 1) * HH + k0);
#pragma unroll
        for (int i = 0; i < 16; i++) { w0[i] = p0[i]; w1[i] = p1[i]; }
    }

    if (tid < HBUF) hsm[0][tid] = 0.0f;
    if (tid == 0) { mbar_init(mb0, 1); mbar_init(mb1, 1); }
    __syncthreads();
    CLUSTER_SYNC_();

    const size_t tstride = (size_t)BB * HH;
    const float* xpp  = g_xp + (size_t)batch * HH + r0 + c;
    float*       outp = out  + (size_t)batch * HH + r0 + c;

    float xv = 0.0f;
    if (!sender && c < 2) xv = *xpp;

    for (int t = 0; t < TT; t++) {
        const unsigned par = (unsigned)t & 1u;
        const uint32_t mbar      = par ? mb1 : mb0;
        const uint32_t peer_mbar = par ? peer_mb1 : peer_mb0;
        const unsigned phase     = ((unsigned)t >> 1) & 1u;

        if (tid == 0) mbar_expect_tx(mbar, 512);

        const ulonglong2* hp = (const ulonglong2*)&hsm[par][HP * c];
        ull a0A = 0ull, a1A = 0ull, a0B = 0ull, a1B = 0ull;
#pragma unroll
        for (int i = 0; i < 4; i++) {
            ulonglong2 hq = hp[i];
            a0A = ffma2(w0[2 * i],     hq.x, a0A);
            a1A = ffma2(w1[2 * i],     hq.x, a1A);
            a0A = ffma2(w0[2 * i + 1], hq.y, a0A);
            a1A = ffma2(w1[2 * i + 1], hq.y, a1A);
        }
#pragma unroll
        for (int i = 4; i < 8; i++) {
            ulonglong2 hq = hp[i];
            a0B = ffma2(w0[2 * i],     hq.x, a0B);
            a1B = ffma2(w1[2 * i],     hq.x, a1B);
            a0B = ffma2(w0[2 * i + 1], hq.y, a0B);
            a1B = ffma2(w1[2 * i + 1], hq.y, a1B);
        }
        float2 u0 = funpack2(fadd2(a0A, a0B));
        float2 u1 = funpack2(fadd2(a1A, a1B));
        float s0 = u0.x + u0.y;
        float s1 = u1.x + u1.y;
#pragma unroll
        for (int m = 1; m < 4; m <<= 1) {
            s0 += __shfl_xor_sync(0xffffffffu, s0, m);
            s1 += __shfl_xor_sync(0xffffffffu, s1, m);
        }

        if (sender) {
            if (c == 0) {
                uint32_t raddr = peer_rsm + (par * (unsigned)RBUF + 2u * (unsigned)gg) * 4u;
                st_async_b64(raddr, fpack2(s0, s1), peer_mbar);
            }
        } else if (c < 2) {
            // Pre-wait: everything not needing the peer partial.
            float base = (c ? s1 : s0) + xv;
            mbar_wait_parity(mbar, phase);
            const int li = 2 * gg + c;
            float pr = rsm[par][li];
            float hn = fast_tanhf(base + pr);
            const unsigned nb = par ^ 1u;
            hsm[nb][HP * (li >> 5) + (li & 31)] = hn;
            outp[(size_t)t * tstride] = hn;
            if (t + 1 < TT)
                xv = xpp[(size_t)(t + 1) * tstride];
        }

        __syncthreads();
    }
    CLUSTER_SYNC_();
}

// ---------------------------------------------------------------------------
// Launch
// ---------------------------------------------------------------------------
extern "C" void kernel_launch(void* const* d_in, const int* in_sizes, int n_in,
                              void* d_out, int out_size)
{
    const float* x    = (const float*)d_in[0];
    const float* Wih  = (const float*)d_in[1];
    const float* Whh  = (const float*)d_in[2];
    const float* b_ih = (const float*)d_in[3];
    const float* b_hh = (const float*)d_in[4];
    float* out = (float*)d_out;

    cudaFuncSetAttribute(xp_gemm_kernel,
                         cudaFuncAttributeMaxDynamicSharedMemorySize, GEMM_SMEM);
    dim3 g1((TT * BB) / 128, HH / 128);
    xp_gemm_kernel<<<g1, 256, GEMM_SMEM>>>(x, Wih, b_ih, b_hh);

    rnn_scan_kernel<<<2 * BB, 512>>>(Whh, out);
}